// round 15
// baseline (speedup 1.0000x reference)
#include <cuda_runtime.h>
#include <cuda_fp16.h>
#include <cstdint>
#include <math.h>

// ----------------------------------------------------------------------------
// SimplePINN forward on GB300 (base sm_103) — HMMA fp16 2-term split, 3-pass.
// R15 = R14 + dual-chunk CTAs: each CTA owns 128 rows as two 64-row chunks
// sharing ONE staged W per layer (halves W staging traffic), grid 7813.
// ----------------------------------------------------------------------------

#define NPOINTS 1000000
#define NBLK1   7813          // ceil(1e6/128); last CTA's chunk1 is masked
#define NCHUNK  15626
#define TPB     512

#define K2S 136               // A/W row stride in halfs (K=128 pad, 17x16B)

// pass1 smem layout (bytes)
#define P1_RED  0             // 16 doubles
#define P1_B0   128           // 128 f
#define P1_FB   640           // 128 f
#define P1_X2   1152          // 128 f  (A cols 128/129, fp32; rebuilt per chunk)
#define P1_W2   1664          // 256 f  (W0 cols 128/129, fp32)
#define P1_A    2688          // A (17408, fp16 single; rebuilt per chunk)
#define P1_W    20096         // W_hi (34816) then W_lo (34816)
#define P1_SMEM 89728
// pass2 smem layout
#define P2_BIAS 0             // 384 f
#define P2_W4   1536          // 256 f
#define P2_B4   2560          // 2 f
#define P2_EXCH 2576          // 512 f
#define P2_A0   4624          // chunk0 A (17408)
#define P2_A1   22032         // chunk1 A (17408)
#define P2_W    39440         // W_hi (34816) then W_lo (34816)
#define P2_SMEM 109072

__device__ __align__(16) __half g_w0img[2][128 * K2S];   // k<128 only
__device__ __align__(16) float g_w0tail[256];             // W0[:,128:130]
__device__ __align__(16) __half g_wimg[3][2][128 * K2S];
__device__ float4 g_y[(size_t)NCHUNK * 2048];
__device__ uint2  g_n[(size_t)NCHUNK * 2048];
__device__ double g_part[NBLK1];
__device__ double g_sumsq;

extern __shared__ __align__(16) char smem[];

// ------------------------------------------------------------ ptx helpers ---
__device__ __forceinline__ uint32_t smem_u32(const void* p) {
    uint32_t a;
    asm("{ .reg .u64 t; cvta.to.shared.u64 t, %1; cvt.u32.u64 %0, t; }" : "=r"(a) : "l"(p));
    return a;
}
__device__ __forceinline__ void ldsm_x4(uint32_t addr, uint32_t r[4]) {
    asm volatile("ldmatrix.sync.aligned.m8n8.x4.shared.b16 {%0,%1,%2,%3}, [%4];"
                 : "=r"(r[0]), "=r"(r[1]), "=r"(r[2]), "=r"(r[3]) : "r"(addr));
}
__device__ __forceinline__ void mma_f16(float* c, const uint32_t* a, uint32_t b0, uint32_t b1) {
    asm volatile("mma.sync.aligned.m16n8k16.row.col.f32.f16.f16.f32 "
                 "{%0,%1,%2,%3}, {%4,%5,%6,%7}, {%8,%9}, {%0,%1,%2,%3};"
                 : "+f"(c[0]), "+f"(c[1]), "+f"(c[2]), "+f"(c[3])
                 : "r"(a[0]), "r"(a[1]), "r"(a[2]), "r"(a[3]), "r"(b0), "r"(b1));
}
__device__ __forceinline__ void cp_async16(uint32_t dst, const void* src) {
    asm volatile("cp.async.cg.shared.global [%0], [%1], 16;" :: "r"(dst), "l"(src));
}
#define CP_COMMIT() asm volatile("cp.async.commit_group;" ::: "memory")
#define CP_WAIT0()  asm volatile("cp.async.wait_group 0;" ::: "memory")

__device__ __forceinline__ uint32_t packh2(float f0, float f1) {
    uint32_t r;
    asm("cvt.rn.f16x2.f32 %0, %1, %2;" : "=r"(r) : "f"(f1), "f"(f0));
    return r;
}
__device__ __forceinline__ uint32_t packbf2(float f0, float f1) {
    uint32_t r;
    asm("cvt.rn.bf16x2.f32 %0, %1, %2;" : "=r"(r) : "f"(f1), "f"(f0));
    return r;
}

// ---------------------------------------------------------------- threefry ---
__device__ __forceinline__ uint32_t rotl32(uint32_t x, int r) { return __funnelshift_l(x, x, r); }
__device__ __forceinline__ uint32_t threefry_bits(uint32_t idx) {
    const uint32_t k0 = 0u, k1 = 42u;
    const uint32_t k2 = k0 ^ k1 ^ 0x1BD11BDAu;
    uint32_t x0 = 0u + k0, x1 = idx + k1;
#define TFR(r) { x0 += x1; x1 = rotl32(x1, r); x1 ^= x0; }
    TFR(13) TFR(15) TFR(26) TFR(6)   x0 += k1; x1 += k2 + 1u;
    TFR(17) TFR(29) TFR(16) TFR(24)  x0 += k2; x1 += k0 + 2u;
    TFR(13) TFR(15) TFR(26) TFR(6)   x0 += k0; x1 += k1 + 3u;
    TFR(17) TFR(29) TFR(16) TFR(24)  x0 += k1; x1 += k2 + 4u;
    TFR(13) TFR(15) TFR(26) TFR(6)   x0 += k2; x1 += k0 + 5u;
#undef TFR
    return x0 ^ x1;
}
__device__ __forceinline__ float erfinv_xla(float x) {
    float w = -__logf(fmaf(-x, x, 1.0f));
    float p;
    if (w < 5.0f) {
        w -= 2.5f;
        p = 2.81022636e-08f;
        p = fmaf(p, w, 3.43273939e-07f);  p = fmaf(p, w, -3.5233877e-06f);
        p = fmaf(p, w, -4.39150654e-06f); p = fmaf(p, w, 0.00021858087f);
        p = fmaf(p, w, -0.00125372503f);  p = fmaf(p, w, -0.00417768164f);
        p = fmaf(p, w, 0.246640727f);     p = fmaf(p, w, 1.50140941f);
    } else {
        w = sqrtf(w) - 3.0f;
        p = -0.000200214257f;
        p = fmaf(p, w, 0.000100950558f);  p = fmaf(p, w, 0.00134934322f);
        p = fmaf(p, w, -0.00367342844f);  p = fmaf(p, w, 0.00573950773f);
        p = fmaf(p, w, -0.0076224613f);   p = fmaf(p, w, 0.00943887047f);
        p = fmaf(p, w, 1.00167406f);      p = fmaf(p, w, 2.83297682f);
    }
    return p * x;
}
__device__ __forceinline__ float noise_at(uint32_t flat) {
    uint32_t bits = threefry_bits(flat);
    float u01 = __uint_as_float((bits >> 9) | 0x3F800000u) - 1.0f;
    const float lo = -0.99999994f;
    float u = fmaxf(lo, fmaf(u01, 1.99999994f, lo));
    return 1.4142135381698608f * erfinv_xla(u);
}
__device__ __forceinline__ float fast_tanh(float x) {
    float y;
    asm("tanh.approx.f32 %0, %1;" : "=f"(y) : "f"(x));
    return y;
}

// -------------------------------------------------------------------- prep ---
__global__ void prep_img_kernel(const float* __restrict__ W0, const float* __restrict__ W1,
                                const float* __restrict__ W2, const float* __restrict__ W3) {
    int i0 = blockIdx.x * blockDim.x + threadIdx.x;
    int st = gridDim.x * blockDim.x;
    for (int idx = i0; idx < 128 * K2S; idx += st) {
        int n = idx / K2S, k = idx - n * K2S;
        float v = (k < 128) ? W0[n * 130 + k] : 0.f;
        __half h = __float2half_rn(v);
        g_w0img[0][idx] = h;
        g_w0img[1][idx] = __float2half_rn(v - __half2float(h));
    }
    for (int idx = i0; idx < 256; idx += st)
        g_w0tail[idx] = W0[(idx >> 1) * 130 + 128 + (idx & 1)];
    for (int L = 0; L < 3; ++L) {
        const float* W = (L == 0) ? W1 : (L == 1) ? W2 : W3;
        for (int idx = i0; idx < 128 * K2S; idx += st) {
            int n = idx / K2S, k = idx - n * K2S;
            float v = (k < 128) ? W[n * 128 + k] : 0.f;
            __half h = __float2half_rn(v);
            g_wimg[L][0][idx] = h;
            g_wimg[L][1][idx] = __float2half_rn(v - __half2float(h));
        }
    }
}

// ------------------------------------------------------------------- pass1 ---
__device__ __forceinline__ float feat_val(int k, float x0, float x1, const float* sFB) {
    if (k < 2) return (k == 0) ? x0 : x1;
    if (k < 130) {
        int j = (k < 66) ? (k - 2) : (k - 66);
        float t = fmaf(x1, sFB[64 + j], x0 * sFB[j]);
        float fr = t - rintf(t);
        float x = 6.2831853071795865f * fr;         // |x| <= pi
        return (k < 66) ? __sinf(x) : __cosf(x);
    }
    return 0.f;
}

// 128-row CTA as two 64-row chunks; warp = 16 rows x 32 cols per chunk.
__global__ void __launch_bounds__(TPB, 2)
pass1_kernel(const float* __restrict__ X, const float* __restrict__ FB,
             const float* __restrict__ b0v) {
    double* sRed = (double*)(smem + P1_RED);
    float* sb0 = (float*)(smem + P1_B0);
    float* sFB = (float*)(smem + P1_FB);
    float* sX2 = (float*)(smem + P1_X2);
    float* sW2 = (float*)(smem + P1_W2);
    const uint32_t sb = smem_u32(smem);

    const int tid = threadIdx.x;
    const int w = tid >> 5, lane = tid & 31;
    const int rg = w >> 2, nq = w & 3;
    const int gr = lane >> 2, qc = (lane & 3) * 2;
    const int blk = blockIdx.x;

    // stage W0 hi/lo (69632 B) via cp.async — serves BOTH chunks
    {
        const float4* src = (const float4*)g_w0img;
        for (int i = tid; i < 69632 / 16; i += TPB)
            cp_async16(sb + P1_W + i * 16, src + i);
        CP_COMMIT();
    }
    if (tid < 128) { sb0[tid] = b0v[tid]; sFB[tid] = FB[tid]; }
    if (tid < 256) sW2[tid] = g_w0tail[tid];
    __syncthreads();   // sFB visible

    const uint32_t arow = sb + P1_A + (rg * 16 + (lane & 15)) * (K2S * 2) + (lane >> 4) * 16;
    const uint32_t brow = sb + P1_W + (lane & 15) * (K2S * 2) + (lane >> 4) * 16;

    double ls = 0.0;
#pragma unroll 1
    for (int c = 0; c < 2; ++c) {
        const long base = (long)blk * 128 + c * 64;
        // build feats A (8 threads per row, 8 col-pairs each)
        {
            int row = tid >> 3, q = tid & 7;
            long rowg = base + row;
            float2 xv = make_float2(0.f, 0.f);
            if (rowg < NPOINTS) xv = ((const float2*)X)[rowg];
            uint32_t* aH = (uint32_t*)(smem + P1_A);
            int cp0 = q * 8;
#pragma unroll
            for (int cp = cp0; cp < cp0 + 8; ++cp) {
                float f0 = feat_val(2 * cp, xv.x, xv.y, sFB);
                float f1 = feat_val(2 * cp + 1, xv.x, xv.y, sFB);
                aH[row * (K2S / 2) + cp] = packh2(f0, f1);
            }
        }
        if (tid < 128) {
            int row = tid >> 1, cc = tid & 1;
            long rowg = base + row;
            float2 xv = make_float2(0.f, 0.f);
            if (rowg < NPOINTS) xv = ((const float2*)X)[rowg];
            sX2[tid] = feat_val(128 + cc, xv.x, xv.y, sFB);
        }
        if (c == 0) CP_WAIT0();
        __syncthreads();

        float acc[4][4];
#pragma unroll
        for (int t = 0; t < 4; ++t)
#pragma unroll
            for (int i = 0; i < 4; ++i) acc[t][i] = 0.f;

#pragma unroll 1
        for (int kt = 0; kt < 8; ++kt) {
            uint32_t ah[4];
            ldsm_x4(arow + kt * 32, ah);
#pragma unroll
            for (int tpl = 0; tpl < 2; ++tpl) {
                int tp = nq * 2 + tpl;
                uint32_t bh[4], bl[4];
                uint32_t ba = brow + tp * 16 * (K2S * 2) + kt * 32;
                ldsm_x4(ba, bh);
                ldsm_x4(ba + 34816, bl);
                mma_f16(acc[2 * tpl],     ah, bh[0], bh[2]);
                mma_f16(acc[2 * tpl + 1], ah, bh[1], bh[3]);
                mma_f16(acc[2 * tpl],     ah, bl[0], bl[2]);
                mma_f16(acc[2 * tpl + 1], ah, bl[1], bl[3]);
            }
        }

        // epilogue: +b0 + fp32 rank-2 tail, masked sum(y^2), y + noise stores
        const size_t tb = ((size_t)((blk * 2 + c) * 16 + w)) * 128;
#pragma unroll
        for (int nt2 = 0; nt2 < 4; ++nt2) {
            int colg = nq * 32 + nt2 * 8 + qc;
            float w00 = sW2[colg * 2], w01 = sW2[colg * 2 + 1];
            float w10 = sW2[colg * 2 + 2], w11 = sW2[colg * 2 + 3];
            float4 yv;
            uint2 nv;
#pragma unroll
            for (int h = 0; h < 2; ++h) {
                int row = rg * 16 + gr + 8 * h;
                long rowg = base + row;
                float a0 = sX2[row * 2], a1 = sX2[row * 2 + 1];
                float c0 = acc[nt2][2 * h]     + sb0[colg]     + a0 * w00 + a1 * w01;
                float c1 = acc[nt2][2 * h + 1] + sb0[colg + 1] + a0 * w10 + a1 * w11;
                if (rowg < NPOINTS) ls += (double)c0 * c0 + (double)c1 * c1;
                if (h == 0) { yv.x = c0; yv.y = c1; } else { yv.z = c0; yv.w = c1; }
                uint32_t fb0 = (uint32_t)(rowg * 128) + colg;
                uint32_t np = packbf2(noise_at(fb0), noise_at(fb0 + 1));
                if (h == 0) nv.x = np; else nv.y = np;
            }
            g_y[tb + nt2 * 32 + lane] = yv;
            g_n[tb + nt2 * 32 + lane] = nv;
        }
        __syncthreads();   // all A reads done before chunk1 rebuild
    }

#pragma unroll
    for (int off = 16; off; off >>= 1) ls += __shfl_down_sync(0xffffffffu, ls, off);
    if (lane == 0) sRed[w] = ls;
    __syncthreads();
    if (w == 0) {
        double v = (lane < 16) ? sRed[lane] : 0.0;
#pragma unroll
        for (int off = 8; off; off >>= 1) v += __shfl_down_sync(0xffffffffu, v, off);
        if (lane == 0) g_part[blk] = v;
    }
}

// ------------------------------------------------------- deterministic sum ---
__global__ void reduce_kernel() {
    __shared__ double s[1024];
    double v = 0.0;
    for (int i = threadIdx.x; i < NBLK1; i += 1024) v += g_part[i];
    s[threadIdx.x] = v;
    __syncthreads();
    for (int o = 512; o > 0; o >>= 1) {
        if (threadIdx.x < o) s[threadIdx.x] += s[threadIdx.x + o];
        __syncthreads();
    }
    if (threadIdx.x == 0) g_sumsq = s[0];
}

// ------------------------------------------------------------------- pass2 ---
// 128-row CTA, chunks share staged W; warp = 16 rows x 32 cols per chunk.
__global__ void __launch_bounds__(TPB, 2)
pass2_kernel(const float* __restrict__ b1, const float* __restrict__ b2,
             const float* __restrict__ b3, const float* __restrict__ W4,
             const float* __restrict__ b4, float* __restrict__ out) {
    float* sBias = (float*)(smem + P2_BIAS);
    float* sW4 = (float*)(smem + P2_W4);
    float* sb4 = (float*)(smem + P2_B4);
    float* exch = (float*)(smem + P2_EXCH);
    const uint32_t sb = smem_u32(smem);

    const int tid = threadIdx.x;
    const int w = tid >> 5, lane = tid & 31;
    const int rg = w >> 2, nq = w & 3;
    const int gr = lane >> 2, qc = (lane & 3) * 2;
    const int blk = blockIdx.x;

    // kick off W(0) staging immediately (overlaps A-build)
    {
        const float4* src = (const float4*)g_wimg[0];
        for (int i = tid; i < 69632 / 16; i += TPB)
            cp_async16(sb + P2_W + i * 16, src + i);
        CP_COMMIT();
    }
    if (tid < 128) { sBias[tid] = b1[tid]; sBias[128 + tid] = b2[tid]; sBias[256 + tid] = b3[tid]; }
    if (tid < 256) sW4[tid] = W4[tid];
    if (tid < 2) sb4[tid] = b4[tid];

    double ss = g_sumsq;
    float power = (float)(ss * (1.0 / 128000000.0));
    float stdv = 0.0f;
    if (isfinite(power) && power > 1.1920929e-07f) stdv = sqrtf(power * 1e-3f);

    const int aoff[2] = {P2_A0, P2_A1};

    // build A0 and A1 = fp16(tanh(y + stdv*noise))
#pragma unroll 1
    for (int c = 0; c < 2; ++c) {
        uint32_t* aH = (uint32_t*)(smem + aoff[c]);
        const size_t tb = ((size_t)((blk * 2 + c) * 16 + w)) * 128;
#pragma unroll
        for (int nt2 = 0; nt2 < 4; ++nt2) {
            float4 yv = g_y[tb + nt2 * 32 + lane];
            uint2 nv = g_n[tb + nt2 * 32 + lane];
            int acol = nq * 16 + nt2 * 4 + (lane & 3);
#pragma unroll
            for (int h = 0; h < 2; ++h) {
                float y0 = (h == 0) ? yv.x : yv.z;
                float y1 = (h == 0) ? yv.y : yv.w;
                uint32_t un = (h == 0) ? nv.x : nv.y;
                float n0 = __uint_as_float(un << 16);
                float n1 = __uint_as_float(un & 0xffff0000u);
                int row = rg * 16 + gr + 8 * h;
                float v0 = fast_tanh(fmaf(n0, stdv, y0));
                float v1 = fast_tanh(fmaf(n1, stdv, y1));
                aH[row * (K2S / 2) + acol] = packh2(v0, v1);
            }
        }
    }

    const uint32_t brow = sb + P2_W + (lane & 15) * (K2S * 2) + (lane >> 4) * 16;
    const uint32_t arow_c = (rg * 16 + (lane & 15)) * (K2S * 2) + (lane >> 4) * 16;
    float acc[4][4];

#pragma unroll 1
    for (int L = 0; L < 3; ++L) {
        CP_WAIT0();          // W(L) staged
        __syncthreads();     // + A writes visible

#pragma unroll 1
        for (int c = 0; c < 2; ++c) {
            const uint32_t arow = sb + aoff[c] + arow_c;
#pragma unroll
            for (int t = 0; t < 4; ++t)
#pragma unroll
                for (int i = 0; i < 4; ++i) acc[t][i] = 0.f;

#pragma unroll 1
            for (int kt = 0; kt < 8; ++kt) {
                uint32_t ah[4];
                ldsm_x4(arow + kt * 32, ah);
#pragma unroll
                for (int tpl = 0; tpl < 2; ++tpl) {
                    int tp = nq * 2 + tpl;
                    uint32_t bh[4], bl[4];
                    uint32_t ba = brow + tp * 16 * (K2S * 2) + kt * 32;
                    ldsm_x4(ba, bh);
                    ldsm_x4(ba + 34816, bl);
                    mma_f16(acc[2 * tpl],     ah, bh[0], bh[2]);
                    mma_f16(acc[2 * tpl + 1], ah, bh[1], bh[3]);
                    mma_f16(acc[2 * tpl],     ah, bl[0], bl[2]);
                    mma_f16(acc[2 * tpl + 1], ah, bl[1], bl[3]);
                }
            }
            __syncthreads();   // A/W reads done (chunk c) before A rewrite

            if (L < 2) {
                if (c == 1) {
                    // all W(L) reads done — stage W(L+1), overlaps epilogue
                    const float4* src = (const float4*)g_wimg[L + 1];
                    for (int i = tid; i < 69632 / 16; i += TPB)
                        cp_async16(sb + P2_W + i * 16, src + i);
                    CP_COMMIT();
                }
                uint32_t* aH = (uint32_t*)(smem + aoff[c]);
#pragma unroll
                for (int nt2 = 0; nt2 < 4; ++nt2) {
                    int colg = nq * 32 + nt2 * 8 + qc;
                    int acol = nq * 16 + nt2 * 4 + (lane & 3);
#pragma unroll
                    for (int h = 0; h < 2; ++h) {
                        float v0 = fast_tanh(acc[nt2][2 * h]     + sBias[L * 128 + colg]);
                        float v1 = fast_tanh(acc[nt2][2 * h + 1] + sBias[L * 128 + colg + 1]);
                        int row = rg * 16 + gr + 8 * h;
                        aH[row * (K2S / 2) + acol] = packh2(v0, v1);
                    }
                }
            } else {
                // final layer: output epilogue for this chunk
                float p00 = 0.f, p01 = 0.f, p10 = 0.f, p11 = 0.f;
#pragma unroll
                for (int nt2 = 0; nt2 < 4; ++nt2) {
#pragma unroll
                    for (int i = 0; i < 2; ++i) {
                        int col = nq * 32 + nt2 * 8 + qc + i;
                        float b = sBias[256 + col];
                        float h0 = fast_tanh(acc[nt2][i] + b);
                        float h1 = fast_tanh(acc[nt2][2 + i] + b);
                        float w0 = sW4[col], w1 = sW4[128 + col];
                        p00 = fmaf(h0, w0, p00); p01 = fmaf(h0, w1, p01);
                        p10 = fmaf(h1, w0, p10); p11 = fmaf(h1, w1, p11);
                    }
                }
#pragma unroll
                for (int m = 1; m <= 2; m <<= 1) {
                    p00 += __shfl_xor_sync(0xffffffffu, p00, m);
                    p01 += __shfl_xor_sync(0xffffffffu, p01, m);
                    p10 += __shfl_xor_sync(0xffffffffu, p10, m);
                    p11 += __shfl_xor_sync(0xffffffffu, p11, m);
                }
                if ((lane & 3) == 0) {
                    int row0 = rg * 16 + gr;
                    exch[(row0 * 4 + nq) * 2 + 0] = p00;
                    exch[(row0 * 4 + nq) * 2 + 1] = p01;
                    exch[((row0 + 8) * 4 + nq) * 2 + 0] = p10;
                    exch[((row0 + 8) * 4 + nq) * 2 + 1] = p11;
                }
                __syncthreads();
                if (tid < 128) {
                    int row = tid >> 1, o = tid & 1;
                    long rowg = (long)blk * 128 + c * 64 + row;
                    if (rowg < NPOINTS) {
                        float v = exch[(row * 4 + 0) * 2 + o] + exch[(row * 4 + 1) * 2 + o]
                                + exch[(row * 4 + 2) * 2 + o] + exch[(row * 4 + 3) * 2 + o] + sb4[o];
                        out[rowg * 2 + o] = v;
                    }
                }
                if (c == 0) __syncthreads();   // exch reuse by chunk1
            }
        }
    }
}

// ------------------------------------------------------------------- host ----
extern "C" void kernel_launch(void* const* d_in, const int* in_sizes, int n_in,
                              void* d_out, int out_size) {
    const float* X  = (const float*)d_in[0];
    const float* FB = (const float*)d_in[1];
    const float* W0 = (const float*)d_in[2];
    const float* b0 = (const float*)d_in[3];
    const float* W1 = (const float*)d_in[4];
    const float* b1 = (const float*)d_in[5];
    const float* W2 = (const float*)d_in[6];
    const float* b2 = (const float*)d_in[7];
    const float* W3 = (const float*)d_in[8];
    const float* b3 = (const float*)d_in[9];
    const float* W4 = (const float*)d_in[10];
    const float* b4 = (const float*)d_in[11];
    float* out = (float*)d_out;

    cudaFuncSetAttribute(pass1_kernel, cudaFuncAttributeMaxDynamicSharedMemorySize, P1_SMEM);
    cudaFuncSetAttribute(pass2_kernel, cudaFuncAttributeMaxDynamicSharedMemorySize, P2_SMEM);

    prep_img_kernel<<<64, 256>>>(W0, W1, W2, W3);
    pass1_kernel<<<NBLK1, TPB, P1_SMEM>>>(X, FB, b0);
    reduce_kernel<<<1, 1024>>>();
    pass2_kernel<<<NBLK1, TPB, P2_SMEM>>>(b1, b2, b3, W4, b4, out);
}

// round 16
// speedup vs baseline: 1.0948x; 1.0948x over previous
#include <cuda_runtime.h>
#include <cuda_fp16.h>
#include <cstdint>
#include <math.h>

// ----------------------------------------------------------------------------
// SimplePINN forward on GB300 (base sm_103) — HMMA fp16 2-term split, 3-pass.
// R16 = R14 (the 1458us champion: 64-row tiles, 512 thr, 16x32 warps,
// 2 CTAs/SM, cp.async overlap, fp16 2-term GEMM) + noise generation split
// 50/50 between passes: pass1 stores bf16 noise for nt2<2, pass2 computes
// fp32 noise inline for nt2>=2 (hidden under pass2's L1-bound mainloop).
// ----------------------------------------------------------------------------

#define NPOINTS 1000000
#define NBLK2   15625         // 1e6/64 exact (both passes)
#define TPB     512

#define K2S 136               // A/W row stride in halfs (K=128 pad, 17x16B)

// pass1 smem layout (bytes)
#define P1_RED  0             // 16 doubles
#define P1_B0   128           // 128 f
#define P1_FB   640           // 128 f
#define P1_X2   1152          // 128 f  (A cols 128/129, fp32)
#define P1_W2   1664          // 256 f  (W0 cols 128/129, fp32)
#define P1_A    2688          // A (17408, fp16 single)
#define P1_W    20096         // W_hi (34816) then W_lo (34816)
#define P1_SMEM 89728
// pass2 smem layout (64-row tile)
#define P2_BIAS 0             // 384 f
#define P2_W4   1536          // 256 f
#define P2_B4   2560          // 2 f
#define P2_EXCH 2576          // 512 f
#define P2_A    4736          // A (17408, fp16 single)
#define P2_W    22144         // W_hi (34816) then W_lo (34816)
#define P2_SMEM 91776

__device__ __align__(16) __half g_w0img[2][128 * K2S];   // k<128 only
__device__ __align__(16) float g_w0tail[256];             // W0[:,128:130]
__device__ __align__(16) __half g_wimg[3][2][128 * K2S];
__device__ float4 g_y[(size_t)NBLK2 * 2048];     // per warp: 128 float4
__device__ uint2  g_n[(size_t)NBLK2 * 2048];     // bf16x2 noise (nt2<2 only)
__device__ double g_part[NBLK2];
__device__ double g_sumsq;

extern __shared__ __align__(16) char smem[];

// ------------------------------------------------------------ ptx helpers ---
__device__ __forceinline__ uint32_t smem_u32(const void* p) {
    uint32_t a;
    asm("{ .reg .u64 t; cvta.to.shared.u64 t, %1; cvt.u32.u64 %0, t; }" : "=r"(a) : "l"(p));
    return a;
}
__device__ __forceinline__ void ldsm_x4(uint32_t addr, uint32_t r[4]) {
    asm volatile("ldmatrix.sync.aligned.m8n8.x4.shared.b16 {%0,%1,%2,%3}, [%4];"
                 : "=r"(r[0]), "=r"(r[1]), "=r"(r[2]), "=r"(r[3]) : "r"(addr));
}
__device__ __forceinline__ void mma_f16(float* c, const uint32_t* a, uint32_t b0, uint32_t b1) {
    asm volatile("mma.sync.aligned.m16n8k16.row.col.f32.f16.f16.f32 "
                 "{%0,%1,%2,%3}, {%4,%5,%6,%7}, {%8,%9}, {%0,%1,%2,%3};"
                 : "+f"(c[0]), "+f"(c[1]), "+f"(c[2]), "+f"(c[3])
                 : "r"(a[0]), "r"(a[1]), "r"(a[2]), "r"(a[3]), "r"(b0), "r"(b1));
}
__device__ __forceinline__ void cp_async16(uint32_t dst, const void* src) {
    asm volatile("cp.async.cg.shared.global [%0], [%1], 16;" :: "r"(dst), "l"(src));
}
#define CP_COMMIT() asm volatile("cp.async.commit_group;" ::: "memory")
#define CP_WAIT0()  asm volatile("cp.async.wait_group 0;" ::: "memory")

// pack two fp32 into fp16x2 (lo = f0, hi = f1) — single cvt instruction
__device__ __forceinline__ uint32_t packh2(float f0, float f1) {
    uint32_t r;
    asm("cvt.rn.f16x2.f32 %0, %1, %2;" : "=r"(r) : "f"(f1), "f"(f0));
    return r;
}
__device__ __forceinline__ uint32_t packbf2(float f0, float f1) {
    uint32_t r;
    asm("cvt.rn.bf16x2.f32 %0, %1, %2;" : "=r"(r) : "f"(f1), "f"(f0));
    return r;
}

// ---------------------------------------------------------------- threefry ---
__device__ __forceinline__ uint32_t rotl32(uint32_t x, int r) { return __funnelshift_l(x, x, r); }
__device__ __forceinline__ uint32_t threefry_bits(uint32_t idx) {
    const uint32_t k0 = 0u, k1 = 42u;
    const uint32_t k2 = k0 ^ k1 ^ 0x1BD11BDAu;
    uint32_t x0 = 0u + k0, x1 = idx + k1;
#define TFR(r) { x0 += x1; x1 = rotl32(x1, r); x1 ^= x0; }
    TFR(13) TFR(15) TFR(26) TFR(6)   x0 += k1; x1 += k2 + 1u;
    TFR(17) TFR(29) TFR(16) TFR(24)  x0 += k2; x1 += k0 + 2u;
    TFR(13) TFR(15) TFR(26) TFR(6)   x0 += k0; x1 += k1 + 3u;
    TFR(17) TFR(29) TFR(16) TFR(24)  x0 += k1; x1 += k2 + 4u;
    TFR(13) TFR(15) TFR(26) TFR(6)   x0 += k2; x1 += k0 + 5u;
#undef TFR
    return x0 ^ x1;
}
__device__ __forceinline__ float erfinv_xla(float x) {
    float w = -__logf(fmaf(-x, x, 1.0f));
    float p;
    if (w < 5.0f) {
        w -= 2.5f;
        p = 2.81022636e-08f;
        p = fmaf(p, w, 3.43273939e-07f);  p = fmaf(p, w, -3.5233877e-06f);
        p = fmaf(p, w, -4.39150654e-06f); p = fmaf(p, w, 0.00021858087f);
        p = fmaf(p, w, -0.00125372503f);  p = fmaf(p, w, -0.00417768164f);
        p = fmaf(p, w, 0.246640727f);     p = fmaf(p, w, 1.50140941f);
    } else {
        w = sqrtf(w) - 3.0f;
        p = -0.000200214257f;
        p = fmaf(p, w, 0.000100950558f);  p = fmaf(p, w, 0.00134934322f);
        p = fmaf(p, w, -0.00367342844f);  p = fmaf(p, w, 0.00573950773f);
        p = fmaf(p, w, -0.0076224613f);   p = fmaf(p, w, 0.00943887047f);
        p = fmaf(p, w, 1.00167406f);      p = fmaf(p, w, 2.83297682f);
    }
    return p * x;
}
__device__ __forceinline__ float noise_at(uint32_t flat) {
    uint32_t bits = threefry_bits(flat);
    float u01 = __uint_as_float((bits >> 9) | 0x3F800000u) - 1.0f;
    const float lo = -0.99999994f;
    float u = fmaxf(lo, fmaf(u01, 1.99999994f, lo));
    return 1.4142135381698608f * erfinv_xla(u);
}
__device__ __forceinline__ float fast_tanh(float x) {
    float y;
    asm("tanh.approx.f32 %0, %1;" : "=f"(y) : "f"(x));
    return y;
}

// -------------------------------------------------------------------- prep ---
__global__ void prep_img_kernel(const float* __restrict__ W0, const float* __restrict__ W1,
                                const float* __restrict__ W2, const float* __restrict__ W3) {
    int i0 = blockIdx.x * blockDim.x + threadIdx.x;
    int st = gridDim.x * blockDim.x;
    for (int idx = i0; idx < 128 * K2S; idx += st) {
        int n = idx / K2S, k = idx - n * K2S;
        float v = (k < 128) ? W0[n * 130 + k] : 0.f;
        __half h = __float2half_rn(v);
        g_w0img[0][idx] = h;
        g_w0img[1][idx] = __float2half_rn(v - __half2float(h));
    }
    for (int idx = i0; idx < 256; idx += st)
        g_w0tail[idx] = W0[(idx >> 1) * 130 + 128 + (idx & 1)];
    for (int L = 0; L < 3; ++L) {
        const float* W = (L == 0) ? W1 : (L == 1) ? W2 : W3;
        for (int idx = i0; idx < 128 * K2S; idx += st) {
            int n = idx / K2S, k = idx - n * K2S;
            float v = (k < 128) ? W[n * 128 + k] : 0.f;
            __half h = __float2half_rn(v);
            g_wimg[L][0][idx] = h;
            g_wimg[L][1][idx] = __float2half_rn(v - __half2float(h));
        }
    }
}

// ------------------------------------------------------------------- pass1 ---
__device__ __forceinline__ float feat_val(int k, float x0, float x1, const float* sFB) {
    if (k < 2) return (k == 0) ? x0 : x1;
    if (k < 130) {
        int j = (k < 66) ? (k - 2) : (k - 66);
        float t = fmaf(x1, sFB[64 + j], x0 * sFB[j]);
        float fr = t - rintf(t);
        float x = 6.2831853071795865f * fr;         // |x| <= pi
        return (k < 66) ? __sinf(x) : __cosf(x);
    }
    return 0.f;
}

// 64-row tile; warp = 16 rows x 32 cols (rg = w>>2, nq = w&3).
__global__ void __launch_bounds__(TPB, 2)
pass1_kernel(const float* __restrict__ X, const float* __restrict__ FB,
             const float* __restrict__ b0v) {
    double* sRed = (double*)(smem + P1_RED);
    float* sb0 = (float*)(smem + P1_B0);
    float* sFB = (float*)(smem + P1_FB);
    float* sX2 = (float*)(smem + P1_X2);
    float* sW2 = (float*)(smem + P1_W2);
    const uint32_t sb = smem_u32(smem);

    const int tid = threadIdx.x;
    const int w = tid >> 5, lane = tid & 31;
    const int rg = w >> 2, nq = w & 3;
    const int gr = lane >> 2, qc = (lane & 3) * 2;
    const int blk = blockIdx.x;

    // stage W0 hi/lo (69632 B) via cp.async — overlaps feats build below
    {
        const float4* src = (const float4*)g_w0img;
        for (int i = tid; i < 69632 / 16; i += TPB)
            cp_async16(sb + P1_W + i * 16, src + i);
        CP_COMMIT();
    }
    if (tid < 128) { sb0[tid] = b0v[tid]; sFB[tid] = FB[tid]; }
    if (tid < 256) sW2[tid] = g_w0tail[tid];
    __syncthreads();   // sFB visible for feats build
    // build feats A (fp16 single; 8 threads per row, 8 col-pairs each)
    {
        int row = tid >> 3, q = tid & 7;
        float2 xv = ((const float2*)X)[blk * 64 + row];
        uint32_t* aH = (uint32_t*)(smem + P1_A);
        int cp0 = q * 8;
#pragma unroll
        for (int cp = cp0; cp < cp0 + 8; ++cp) {
            float f0 = feat_val(2 * cp, xv.x, xv.y, sFB);
            float f1 = feat_val(2 * cp + 1, xv.x, xv.y, sFB);
            aH[row * (K2S / 2) + cp] = packh2(f0, f1);
        }
    }
    // feature cols 128/129 (fp32 tail)
    if (tid < 128) {
        int row = tid >> 1, c = tid & 1;
        float2 xv = ((const float2*)X)[blk * 64 + row];
        sX2[tid] = feat_val(128 + c, xv.x, xv.y, sFB);
    }
    CP_WAIT0();
    __syncthreads();

    float acc[4][4];
#pragma unroll
    for (int t = 0; t < 4; ++t)
#pragma unroll
        for (int i = 0; i < 4; ++i) acc[t][i] = 0.f;

    const uint32_t arow = sb + P1_A + (rg * 16 + (lane & 15)) * (K2S * 2) + (lane >> 4) * 16;
    const uint32_t brow = sb + P1_W + (lane & 15) * (K2S * 2) + (lane >> 4) * 16;
#pragma unroll 1
    for (int kt = 0; kt < 8; ++kt) {
        uint32_t ah[4];
        ldsm_x4(arow + kt * 32, ah);
#pragma unroll
        for (int tpl = 0; tpl < 2; ++tpl) {
            int tp = nq * 2 + tpl;
            uint32_t bh[4], bl[4];
            uint32_t ba = brow + tp * 16 * (K2S * 2) + kt * 32;
            ldsm_x4(ba, bh);
            ldsm_x4(ba + 34816, bl);
            mma_f16(acc[2 * tpl],     ah, bh[0], bh[2]);
            mma_f16(acc[2 * tpl + 1], ah, bh[1], bh[3]);
            mma_f16(acc[2 * tpl],     ah, bl[0], bl[2]);
            mma_f16(acc[2 * tpl + 1], ah, bl[1], bl[3]);
        }
    }

    // epilogue: +b0 + fp32 rank-2 tail, sum(y^2), y stores; noise only nt2<2
    double ls = 0.0;
    const size_t tb = ((size_t)(blk * 16 + w)) * 128;
#pragma unroll
    for (int nt2 = 0; nt2 < 4; ++nt2) {
        int colg = nq * 32 + nt2 * 8 + qc;
        float w00 = sW2[colg * 2], w01 = sW2[colg * 2 + 1];
        float w10 = sW2[colg * 2 + 2], w11 = sW2[colg * 2 + 3];
        float4 yv;
        uint2 nv;
#pragma unroll
        for (int h = 0; h < 2; ++h) {
            int row = rg * 16 + gr + 8 * h;
            float a0 = sX2[row * 2], a1 = sX2[row * 2 + 1];
            float c0 = acc[nt2][2 * h]     + sb0[colg]     + a0 * w00 + a1 * w01;
            float c1 = acc[nt2][2 * h + 1] + sb0[colg + 1] + a0 * w10 + a1 * w11;
            ls += (double)c0 * c0 + (double)c1 * c1;
            if (h == 0) { yv.x = c0; yv.y = c1; } else { yv.z = c0; yv.w = c1; }
            if (nt2 < 2) {
                uint32_t fb0 = (uint32_t)((blk * 64 + row) * 128) + colg;
                uint32_t np = packbf2(noise_at(fb0), noise_at(fb0 + 1));
                if (h == 0) nv.x = np; else nv.y = np;
            }
        }
        g_y[tb + nt2 * 32 + lane] = yv;
        if (nt2 < 2) g_n[tb + nt2 * 32 + lane] = nv;
    }
#pragma unroll
    for (int off = 16; off; off >>= 1) ls += __shfl_down_sync(0xffffffffu, ls, off);
    if (lane == 0) sRed[w] = ls;
    __syncthreads();
    if (w == 0) {
        double v = (lane < 16) ? sRed[lane] : 0.0;
#pragma unroll
        for (int off = 8; off; off >>= 1) v += __shfl_down_sync(0xffffffffu, v, off);
        if (lane == 0) g_part[blk] = v;
    }
}

// ------------------------------------------------------- deterministic sum ---
__global__ void reduce_kernel() {
    __shared__ double s[1024];
    double v = 0.0;
    for (int i = threadIdx.x; i < NBLK2; i += 1024) v += g_part[i];
    s[threadIdx.x] = v;
    __syncthreads();
    for (int o = 512; o > 0; o >>= 1) {
        if (threadIdx.x < o) s[threadIdx.x] += s[threadIdx.x + o];
        __syncthreads();
    }
    if (threadIdx.x == 0) g_sumsq = s[0];
}

// ------------------------------------------------------------------- pass2 ---
// 64-row tile; warp = 16 rows x 32 cols (rg = w>>2, nq = w&3).
__global__ void __launch_bounds__(TPB, 2)
pass2_kernel(const float* __restrict__ b1, const float* __restrict__ b2,
             const float* __restrict__ b3, const float* __restrict__ W4,
             const float* __restrict__ b4, float* __restrict__ out) {
    float* sBias = (float*)(smem + P2_BIAS);
    float* sW4 = (float*)(smem + P2_W4);
    float* sb4 = (float*)(smem + P2_B4);
    float* exch = (float*)(smem + P2_EXCH);
    const uint32_t sb = smem_u32(smem);

    const int tid = threadIdx.x;
    const int w = tid >> 5, lane = tid & 31;
    const int rg = w >> 2, nq = w & 3;
    const int gr = lane >> 2, qc = (lane & 3) * 2;
    const int blk = blockIdx.x;

    // kick off W(0) staging immediately (overlaps A-build)
    {
        const float4* src = (const float4*)g_wimg[0];
        for (int i = tid; i < 69632 / 16; i += TPB)
            cp_async16(sb + P2_W + i * 16, src + i);
        CP_COMMIT();
    }
    if (tid < 128) { sBias[tid] = b1[tid]; sBias[128 + tid] = b2[tid]; sBias[256 + tid] = b3[tid]; }
    if (tid < 256) sW4[tid] = W4[tid];
    if (tid < 2) sb4[tid] = b4[tid];

    double ss = g_sumsq;
    float power = (float)(ss * (1.0 / 128000000.0));
    float stdv = 0.0f;
    if (isfinite(power) && power > 1.1920929e-07f) stdv = sqrtf(power * 1e-3f);

    // build A = fp16(tanh(y + stdv*noise)); noise: load (nt2<2) / compute (nt2>=2)
    {
        uint32_t* aH = (uint32_t*)(smem + P2_A);
        const size_t tb = ((size_t)(blk * 16 + w)) * 128;
#pragma unroll
        for (int nt2 = 0; nt2 < 4; ++nt2) {
            float4 yv = g_y[tb + nt2 * 32 + lane];
            int colg = nq * 32 + nt2 * 8 + qc;
            int acol = nq * 16 + nt2 * 4 + (lane & 3);
            uint2 nv = make_uint2(0u, 0u);
            if (nt2 < 2) nv = g_n[tb + nt2 * 32 + lane];
#pragma unroll
            for (int h = 0; h < 2; ++h) {
                float y0 = (h == 0) ? yv.x : yv.z;
                float y1 = (h == 0) ? yv.y : yv.w;
                int row = rg * 16 + gr + 8 * h;
                float n0, n1;
                if (nt2 < 2) {
                    uint32_t un = (h == 0) ? nv.x : nv.y;
                    n0 = __uint_as_float(un << 16);
                    n1 = __uint_as_float(un & 0xffff0000u);
                } else {
                    uint32_t fb0 = (uint32_t)((blk * 64 + row) * 128) + colg;
                    n0 = noise_at(fb0);
                    n1 = noise_at(fb0 + 1);
                }
                float v0 = fast_tanh(fmaf(n0, stdv, y0));
                float v1 = fast_tanh(fmaf(n1, stdv, y1));
                aH[row * (K2S / 2) + acol] = packh2(v0, v1);
            }
        }
    }

    const uint32_t arow = sb + P2_A + (rg * 16 + (lane & 15)) * (K2S * 2) + (lane >> 4) * 16;
    const uint32_t brow = sb + P2_W + (lane & 15) * (K2S * 2) + (lane >> 4) * 16;
    float acc[4][4];

#pragma unroll 1
    for (int L = 0; L < 3; ++L) {
        CP_WAIT0();          // W(L) staged
        __syncthreads();     // + A writes visible

#pragma unroll
        for (int t = 0; t < 4; ++t)
#pragma unroll
            for (int i = 0; i < 4; ++i) acc[t][i] = 0.f;

#pragma unroll 1
        for (int kt = 0; kt < 8; ++kt) {
            uint32_t ah[4];
            ldsm_x4(arow + kt * 32, ah);
#pragma unroll
            for (int tpl = 0; tpl < 2; ++tpl) {
                int tp = nq * 2 + tpl;
                uint32_t bh[4], bl[4];
                uint32_t ba = brow + tp * 16 * (K2S * 2) + kt * 32;
                ldsm_x4(ba, bh);
                ldsm_x4(ba + 34816, bl);
                mma_f16(acc[2 * tpl],     ah, bh[0], bh[2]);
                mma_f16(acc[2 * tpl + 1], ah, bh[1], bh[3]);
                mma_f16(acc[2 * tpl],     ah, bl[0], bl[2]);
                mma_f16(acc[2 * tpl + 1], ah, bl[1], bl[3]);
            }
        }
        __syncthreads();   // all A/W reads done before A rewrite / W restage

        if (L < 2) {
            // start W(L+1) staging now — overlaps the epilogue below
            {
                const float4* src = (const float4*)g_wimg[L + 1];
                for (int i = tid; i < 69632 / 16; i += TPB)
                    cp_async16(sb + P2_W + i * 16, src + i);
                CP_COMMIT();
            }
            uint32_t* aH = (uint32_t*)(smem + P2_A);
#pragma unroll
            for (int nt2 = 0; nt2 < 4; ++nt2) {
                int colg = nq * 32 + nt2 * 8 + qc;
                int acol = nq * 16 + nt2 * 4 + (lane & 3);
#pragma unroll
                for (int h = 0; h < 2; ++h) {
                    float v0 = fast_tanh(acc[nt2][2 * h]     + sBias[L * 128 + colg]);
                    float v1 = fast_tanh(acc[nt2][2 * h + 1] + sBias[L * 128 + colg + 1]);
                    int row = rg * 16 + gr + 8 * h;
                    aH[row * (K2S / 2) + acol] = packh2(v0, v1);
                }
            }
        }
    }

    // final activations + output partials over this warp's 32 cols
    float p00 = 0.f, p01 = 0.f, p10 = 0.f, p11 = 0.f;
#pragma unroll
    for (int nt2 = 0; nt2 < 4; ++nt2) {
#pragma unroll
        for (int i = 0; i < 2; ++i) {
            int col = nq * 32 + nt2 * 8 + qc + i;
            float b = sBias[256 + col];
            float h0 = fast_tanh(acc[nt2][i] + b);
            float h1 = fast_tanh(acc[nt2][2 + i] + b);
            float w0 = sW4[col], w1 = sW4[128 + col];
            p00 = fmaf(h0, w0, p00); p01 = fmaf(h0, w1, p01);
            p10 = fmaf(h1, w0, p10); p11 = fmaf(h1, w1, p11);
        }
    }
#pragma unroll
    for (int m = 1; m <= 2; m <<= 1) {
        p00 += __shfl_xor_sync(0xffffffffu, p00, m);
        p01 += __shfl_xor_sync(0xffffffffu, p01, m);
        p10 += __shfl_xor_sync(0xffffffffu, p10, m);
        p11 += __shfl_xor_sync(0xffffffffu, p11, m);
    }
    if ((lane & 3) == 0) {
        int row0 = rg * 16 + gr;
        exch[(row0 * 4 + nq) * 2 + 0] = p00;
        exch[(row0 * 4 + nq) * 2 + 1] = p01;
        exch[((row0 + 8) * 4 + nq) * 2 + 0] = p10;
        exch[((row0 + 8) * 4 + nq) * 2 + 1] = p11;
    }
    __syncthreads();
    if (tid < 128) {
        int row = tid >> 1, o = tid & 1;
        long rowg = (long)blk * 64 + row;
        float v = exch[(row * 4 + 0) * 2 + o] + exch[(row * 4 + 1) * 2 + o]
                + exch[(row * 4 + 2) * 2 + o] + exch[(row * 4 + 3) * 2 + o] + sb4[o];
        out[rowg * 2 + o] = v;
    }
}

// ------------------------------------------------------------------- host ----
extern "C" void kernel_launch(void* const* d_in, const int* in_sizes, int n_in,
                              void* d_out, int out_size) {
    const float* X  = (const float*)d_in[0];
    const float* FB = (const float*)d_in[1];
    const float* W0 = (const float*)d_in[2];
    const float* b0 = (const float*)d_in[3];
    const float* W1 = (const float*)d_in[4];
    const float* b1 = (const float*)d_in[5];
    const float* W2 = (const float*)d_in[6];
    const float* b2 = (const float*)d_in[7];
    const float* W3 = (const float*)d_in[8];
    const float* b3 = (const float*)d_in[9];
    const float* W4 = (const float*)d_in[10];
    const float* b4 = (const float*)d_in[11];
    float* out = (float*)d_out;

    cudaFuncSetAttribute(pass1_kernel, cudaFuncAttributeMaxDynamicSharedMemorySize, P1_SMEM);
    cudaFuncSetAttribute(pass2_kernel, cudaFuncAttributeMaxDynamicSharedMemorySize, P2_SMEM);

    prep_img_kernel<<<64, 256>>>(W0, W1, W2, W3);
    pass1_kernel<<<NBLK2, TPB, P1_SMEM>>>(X, FB, b0);
    reduce_kernel<<<1, 1024>>>();
    pass2_kernel<<<NBLK2, TPB, P2_SMEM>>>(b1, b2, b3, W4, b4, out);
}

// round 17
// speedup vs baseline: 1.1277x; 1.0300x over previous
#include <cuda_runtime.h>
#include <cuda_fp16.h>
#include <cstdint>
#include <math.h>

// ----------------------------------------------------------------------------
// SimplePINN forward on GB300 (base sm_103) — HMMA fp16 2-term split, 3-pass.
// R17 = R14 (1458us champion: 64-row tiles, 512 thr, 16x32 warps, 2 CTAs/SM,
// cp.async overlap, fp16 2-term GEMM, noise fully in pass1) + fused scratch:
// y stored fp16x2 and packed with bf16x2 noise into ONE uint4 per 4 elements
// (scratch 640MB -> 256MB; one LDG.128/STG.128 per nt2 instead of two).
// ----------------------------------------------------------------------------

#define NPOINTS 1000000
#define NBLK2   15625         // 1e6/64 exact (both passes)
#define TPB     512

#define K2S 136               // A/W row stride in halfs (K=128 pad, 17x16B)

// pass1 smem layout (bytes)
#define P1_RED  0             // 16 doubles
#define P1_B0   128           // 128 f
#define P1_FB   640           // 128 f
#define P1_X2   1152          // 128 f  (A cols 128/129, fp32)
#define P1_W2   1664          // 256 f  (W0 cols 128/129, fp32)
#define P1_A    2688          // A (17408, fp16 single)
#define P1_W    20096         // W_hi (34816) then W_lo (34816)
#define P1_SMEM 89728
// pass2 smem layout (64-row tile)
#define P2_BIAS 0             // 384 f
#define P2_W4   1536          // 256 f
#define P2_B4   2560          // 2 f
#define P2_EXCH 2576          // 512 f
#define P2_A    4736          // A (17408, fp16 single)
#define P2_W    22144         // W_hi (34816) then W_lo (34816)
#define P2_SMEM 91776

__device__ __align__(16) __half g_w0img[2][128 * K2S];   // k<128 only
__device__ __align__(16) float g_w0tail[256];             // W0[:,128:130]
__device__ __align__(16) __half g_wimg[3][2][128 * K2S];
// fused scratch: per warp-nt2-lane one uint4 = {y01 fp16x2, y23 fp16x2,
//                                               n01 bf16x2, n23 bf16x2}
__device__ uint4  g_s[(size_t)NBLK2 * 2048];
__device__ double g_part[NBLK2];
__device__ double g_sumsq;

extern __shared__ __align__(16) char smem[];

// ------------------------------------------------------------ ptx helpers ---
__device__ __forceinline__ uint32_t smem_u32(const void* p) {
    uint32_t a;
    asm("{ .reg .u64 t; cvta.to.shared.u64 t, %1; cvt.u32.u64 %0, t; }" : "=r"(a) : "l"(p));
    return a;
}
__device__ __forceinline__ void ldsm_x4(uint32_t addr, uint32_t r[4]) {
    asm volatile("ldmatrix.sync.aligned.m8n8.x4.shared.b16 {%0,%1,%2,%3}, [%4];"
                 : "=r"(r[0]), "=r"(r[1]), "=r"(r[2]), "=r"(r[3]) : "r"(addr));
}
__device__ __forceinline__ void mma_f16(float* c, const uint32_t* a, uint32_t b0, uint32_t b1) {
    asm volatile("mma.sync.aligned.m16n8k16.row.col.f32.f16.f16.f32 "
                 "{%0,%1,%2,%3}, {%4,%5,%6,%7}, {%8,%9}, {%0,%1,%2,%3};"
                 : "+f"(c[0]), "+f"(c[1]), "+f"(c[2]), "+f"(c[3])
                 : "r"(a[0]), "r"(a[1]), "r"(a[2]), "r"(a[3]), "r"(b0), "r"(b1));
}
__device__ __forceinline__ void cp_async16(uint32_t dst, const void* src) {
    asm volatile("cp.async.cg.shared.global [%0], [%1], 16;" :: "r"(dst), "l"(src));
}
#define CP_COMMIT() asm volatile("cp.async.commit_group;" ::: "memory")
#define CP_WAIT0()  asm volatile("cp.async.wait_group 0;" ::: "memory")

// pack two fp32 into fp16x2 (lo = f0, hi = f1)
__device__ __forceinline__ uint32_t packh2(float f0, float f1) {
    uint32_t r;
    asm("cvt.rn.f16x2.f32 %0, %1, %2;" : "=r"(r) : "f"(f1), "f"(f0));
    return r;
}
__device__ __forceinline__ uint32_t packbf2(float f0, float f1) {
    uint32_t r;
    asm("cvt.rn.bf16x2.f32 %0, %1, %2;" : "=r"(r) : "f"(f1), "f"(f0));
    return r;
}

// ---------------------------------------------------------------- threefry ---
__device__ __forceinline__ uint32_t rotl32(uint32_t x, int r) { return __funnelshift_l(x, x, r); }
__device__ __forceinline__ uint32_t threefry_bits(uint32_t idx) {
    const uint32_t k0 = 0u, k1 = 42u;
    const uint32_t k2 = k0 ^ k1 ^ 0x1BD11BDAu;
    uint32_t x0 = 0u + k0, x1 = idx + k1;
#define TFR(r) { x0 += x1; x1 = rotl32(x1, r); x1 ^= x0; }
    TFR(13) TFR(15) TFR(26) TFR(6)   x0 += k1; x1 += k2 + 1u;
    TFR(17) TFR(29) TFR(16) TFR(24)  x0 += k2; x1 += k0 + 2u;
    TFR(13) TFR(15) TFR(26) TFR(6)   x0 += k0; x1 += k1 + 3u;
    TFR(17) TFR(29) TFR(16) TFR(24)  x0 += k1; x1 += k2 + 4u;
    TFR(13) TFR(15) TFR(26) TFR(6)   x0 += k2; x1 += k0 + 5u;
#undef TFR
    return x0 ^ x1;
}
__device__ __forceinline__ float erfinv_xla(float x) {
    float w = -__logf(fmaf(-x, x, 1.0f));
    float p;
    if (w < 5.0f) {
        w -= 2.5f;
        p = 2.81022636e-08f;
        p = fmaf(p, w, 3.43273939e-07f);  p = fmaf(p, w, -3.5233877e-06f);
        p = fmaf(p, w, -4.39150654e-06f); p = fmaf(p, w, 0.00021858087f);
        p = fmaf(p, w, -0.00125372503f);  p = fmaf(p, w, -0.00417768164f);
        p = fmaf(p, w, 0.246640727f);     p = fmaf(p, w, 1.50140941f);
    } else {
        w = sqrtf(w) - 3.0f;
        p = -0.000200214257f;
        p = fmaf(p, w, 0.000100950558f);  p = fmaf(p, w, 0.00134934322f);
        p = fmaf(p, w, -0.00367342844f);  p = fmaf(p, w, 0.00573950773f);
        p = fmaf(p, w, -0.0076224613f);   p = fmaf(p, w, 0.00943887047f);
        p = fmaf(p, w, 1.00167406f);      p = fmaf(p, w, 2.83297682f);
    }
    return p * x;
}
__device__ __forceinline__ float noise_at(uint32_t flat) {
    uint32_t bits = threefry_bits(flat);
    float u01 = __uint_as_float((bits >> 9) | 0x3F800000u) - 1.0f;
    const float lo = -0.99999994f;
    float u = fmaxf(lo, fmaf(u01, 1.99999994f, lo));
    return 1.4142135381698608f * erfinv_xla(u);
}
__device__ __forceinline__ float fast_tanh(float x) {
    float y;
    asm("tanh.approx.f32 %0, %1;" : "=f"(y) : "f"(x));
    return y;
}

// -------------------------------------------------------------------- prep ---
__global__ void prep_img_kernel(const float* __restrict__ W0, const float* __restrict__ W1,
                                const float* __restrict__ W2, const float* __restrict__ W3) {
    int i0 = blockIdx.x * blockDim.x + threadIdx.x;
    int st = gridDim.x * blockDim.x;
    for (int idx = i0; idx < 128 * K2S; idx += st) {
        int n = idx / K2S, k = idx - n * K2S;
        float v = (k < 128) ? W0[n * 130 + k] : 0.f;
        __half h = __float2half_rn(v);
        g_w0img[0][idx] = h;
        g_w0img[1][idx] = __float2half_rn(v - __half2float(h));
    }
    for (int idx = i0; idx < 256; idx += st)
        g_w0tail[idx] = W0[(idx >> 1) * 130 + 128 + (idx & 1)];
    for (int L = 0; L < 3; ++L) {
        const float* W = (L == 0) ? W1 : (L == 1) ? W2 : W3;
        for (int idx = i0; idx < 128 * K2S; idx += st) {
            int n = idx / K2S, k = idx - n * K2S;
            float v = (k < 128) ? W[n * 128 + k] : 0.f;
            __half h = __float2half_rn(v);
            g_wimg[L][0][idx] = h;
            g_wimg[L][1][idx] = __float2half_rn(v - __half2float(h));
        }
    }
}

// ------------------------------------------------------------------- pass1 ---
__device__ __forceinline__ float feat_val(int k, float x0, float x1, const float* sFB) {
    if (k < 2) return (k == 0) ? x0 : x1;
    if (k < 130) {
        int j = (k < 66) ? (k - 2) : (k - 66);
        float t = fmaf(x1, sFB[64 + j], x0 * sFB[j]);
        float fr = t - rintf(t);
        float x = 6.2831853071795865f * fr;         // |x| <= pi
        return (k < 66) ? __sinf(x) : __cosf(x);
    }
    return 0.f;
}

// 64-row tile; warp = 16 rows x 32 cols (rg = w>>2, nq = w&3).
__global__ void __launch_bounds__(TPB, 2)
pass1_kernel(const float* __restrict__ X, const float* __restrict__ FB,
             const float* __restrict__ b0v) {
    double* sRed = (double*)(smem + P1_RED);
    float* sb0 = (float*)(smem + P1_B0);
    float* sFB = (float*)(smem + P1_FB);
    float* sX2 = (float*)(smem + P1_X2);
    float* sW2 = (float*)(smem + P1_W2);
    const uint32_t sb = smem_u32(smem);

    const int tid = threadIdx.x;
    const int w = tid >> 5, lane = tid & 31;
    const int rg = w >> 2, nq = w & 3;
    const int gr = lane >> 2, qc = (lane & 3) * 2;
    const int blk = blockIdx.x;

    // stage W0 hi/lo (69632 B) via cp.async — overlaps feats build below
    {
        const float4* src = (const float4*)g_w0img;
        for (int i = tid; i < 69632 / 16; i += TPB)
            cp_async16(sb + P1_W + i * 16, src + i);
        CP_COMMIT();
    }
    if (tid < 128) { sb0[tid] = b0v[tid]; sFB[tid] = FB[tid]; }
    if (tid < 256) sW2[tid] = g_w0tail[tid];
    __syncthreads();   // sFB visible for feats build
    // build feats A (fp16 single; 8 threads per row, 8 col-pairs each)
    {
        int row = tid >> 3, q = tid & 7;
        float2 xv = ((const float2*)X)[blk * 64 + row];
        uint32_t* aH = (uint32_t*)(smem + P1_A);
        int cp0 = q * 8;
#pragma unroll
        for (int cp = cp0; cp < cp0 + 8; ++cp) {
            float f0 = feat_val(2 * cp, xv.x, xv.y, sFB);
            float f1 = feat_val(2 * cp + 1, xv.x, xv.y, sFB);
            aH[row * (K2S / 2) + cp] = packh2(f0, f1);
        }
    }
    // feature cols 128/129 (fp32 tail)
    if (tid < 128) {
        int row = tid >> 1, c = tid & 1;
        float2 xv = ((const float2*)X)[blk * 64 + row];
        sX2[tid] = feat_val(128 + c, xv.x, xv.y, sFB);
    }
    CP_WAIT0();
    __syncthreads();

    float acc[4][4];
#pragma unroll
    for (int t = 0; t < 4; ++t)
#pragma unroll
        for (int i = 0; i < 4; ++i) acc[t][i] = 0.f;

    const uint32_t arow = sb + P1_A + (rg * 16 + (lane & 15)) * (K2S * 2) + (lane >> 4) * 16;
    const uint32_t brow = sb + P1_W + (lane & 15) * (K2S * 2) + (lane >> 4) * 16;
#pragma unroll 1
    for (int kt = 0; kt < 8; ++kt) {
        uint32_t ah[4];
        ldsm_x4(arow + kt * 32, ah);
#pragma unroll
        for (int tpl = 0; tpl < 2; ++tpl) {
            int tp = nq * 2 + tpl;
            uint32_t bh[4], bl[4];
            uint32_t ba = brow + tp * 16 * (K2S * 2) + kt * 32;
            ldsm_x4(ba, bh);
            ldsm_x4(ba + 34816, bl);
            mma_f16(acc[2 * tpl],     ah, bh[0], bh[2]);
            mma_f16(acc[2 * tpl + 1], ah, bh[1], bh[3]);
            mma_f16(acc[2 * tpl],     ah, bl[0], bl[2]);
            mma_f16(acc[2 * tpl + 1], ah, bl[1], bl[3]);
        }
    }

    // epilogue: +b0 + fp32 rank-2 tail, sum(y^2), fused y+noise uint4 store
    double ls = 0.0;
    const size_t tb = ((size_t)(blk * 16 + w)) * 128;
#pragma unroll
    for (int nt2 = 0; nt2 < 4; ++nt2) {
        int colg = nq * 32 + nt2 * 8 + qc;
        float w00 = sW2[colg * 2], w01 = sW2[colg * 2 + 1];
        float w10 = sW2[colg * 2 + 2], w11 = sW2[colg * 2 + 3];
        float yv[4];
        uint32_t nb[2];
#pragma unroll
        for (int h = 0; h < 2; ++h) {
            int row = rg * 16 + gr + 8 * h;
            float a0 = sX2[row * 2], a1 = sX2[row * 2 + 1];
            float c0 = acc[nt2][2 * h]     + sb0[colg]     + a0 * w00 + a1 * w01;
            float c1 = acc[nt2][2 * h + 1] + sb0[colg + 1] + a0 * w10 + a1 * w11;
            ls += (double)c0 * c0 + (double)c1 * c1;
            yv[2 * h] = c0; yv[2 * h + 1] = c1;
            uint32_t fb0 = (uint32_t)((blk * 64 + row) * 128) + colg;
            nb[h] = packbf2(noise_at(fb0), noise_at(fb0 + 1));
        }
        uint4 sv;
        sv.x = packh2(yv[0], yv[1]);
        sv.y = packh2(yv[2], yv[3]);
        sv.z = nb[0];
        sv.w = nb[1];
        g_s[tb + nt2 * 32 + lane] = sv;
    }
#pragma unroll
    for (int off = 16; off; off >>= 1) ls += __shfl_down_sync(0xffffffffu, ls, off);
    if (lane == 0) sRed[w] = ls;
    __syncthreads();
    if (w == 0) {
        double v = (lane < 16) ? sRed[lane] : 0.0;
#pragma unroll
        for (int off = 8; off; off >>= 1) v += __shfl_down_sync(0xffffffffu, v, off);
        if (lane == 0) g_part[blk] = v;
    }
}

// ------------------------------------------------------- deterministic sum ---
__global__ void reduce_kernel() {
    __shared__ double s[1024];
    double v = 0.0;
    for (int i = threadIdx.x; i < NBLK2; i += 1024) v += g_part[i];
    s[threadIdx.x] = v;
    __syncthreads();
    for (int o = 512; o > 0; o >>= 1) {
        if (threadIdx.x < o) s[threadIdx.x] += s[threadIdx.x + o];
        __syncthreads();
    }
    if (threadIdx.x == 0) g_sumsq = s[0];
}

// ------------------------------------------------------------------- pass2 ---
// 64-row tile; warp = 16 rows x 32 cols (rg = w>>2, nq = w&3).
__global__ void __launch_bounds__(TPB, 2)
pass2_kernel(const float* __restrict__ b1, const float* __restrict__ b2,
             const float* __restrict__ b3, const float* __restrict__ W4,
             const float* __restrict__ b4, float* __restrict__ out) {
    float* sBias = (float*)(smem + P2_BIAS);
    float* sW4 = (float*)(smem + P2_W4);
    float* sb4 = (float*)(smem + P2_B4);
    float* exch = (float*)(smem + P2_EXCH);
    const uint32_t sb = smem_u32(smem);

    const int tid = threadIdx.x;
    const int w = tid >> 5, lane = tid & 31;
    const int rg = w >> 2, nq = w & 3;
    const int gr = lane >> 2, qc = (lane & 3) * 2;
    const int blk = blockIdx.x;

    // kick off W(0) staging immediately (overlaps A-build)
    {
        const float4* src = (const float4*)g_wimg[0];
        for (int i = tid; i < 69632 / 16; i += TPB)
            cp_async16(sb + P2_W + i * 16, src + i);
        CP_COMMIT();
    }
    if (tid < 128) { sBias[tid] = b1[tid]; sBias[128 + tid] = b2[tid]; sBias[256 + tid] = b3[tid]; }
    if (tid < 256) sW4[tid] = W4[tid];
    if (tid < 2) sb4[tid] = b4[tid];

    double ss = g_sumsq;
    float power = (float)(ss * (1.0 / 128000000.0));
    float stdv = 0.0f;
    if (isfinite(power) && power > 1.1920929e-07f) stdv = sqrtf(power * 1e-3f);

    // build A = fp16(tanh(y + stdv*noise)) from fused uint4 scratch
    {
        uint32_t* aH = (uint32_t*)(smem + P2_A);
        const size_t tb = ((size_t)(blk * 16 + w)) * 128;
#pragma unroll
        for (int nt2 = 0; nt2 < 4; ++nt2) {
            uint4 sv = g_s[tb + nt2 * 32 + lane];
            int acol = nq * 16 + nt2 * 4 + (lane & 3);
#pragma unroll
            for (int h = 0; h < 2; ++h) {
                uint32_t yp = (h == 0) ? sv.x : sv.y;
                uint32_t un = (h == 0) ? sv.z : sv.w;
                float2 yf = __half22float2(*(__half2*)&yp);
                float n0 = __uint_as_float(un << 16);
                float n1 = __uint_as_float(un & 0xffff0000u);
                int row = rg * 16 + gr + 8 * h;
                float v0 = fast_tanh(fmaf(n0, stdv, yf.x));
                float v1 = fast_tanh(fmaf(n1, stdv, yf.y));
                aH[row * (K2S / 2) + acol] = packh2(v0, v1);
            }
        }
    }

    const uint32_t arow = sb + P2_A + (rg * 16 + (lane & 15)) * (K2S * 2) + (lane >> 4) * 16;
    const uint32_t brow = sb + P2_W + (lane & 15) * (K2S * 2) + (lane >> 4) * 16;
    float acc[4][4];

#pragma unroll 1
    for (int L = 0; L < 3; ++L) {
        CP_WAIT0();          // W(L) staged
        __syncthreads();     // + A writes visible

#pragma unroll
        for (int t = 0; t < 4; ++t)
#pragma unroll
            for (int i = 0; i < 4; ++i) acc[t][i] = 0.f;

#pragma unroll 1
        for (int kt = 0; kt < 8; ++kt) {
            uint32_t ah[4];
            ldsm_x4(arow + kt * 32, ah);
#pragma unroll
            for (int tpl = 0; tpl < 2; ++tpl) {
                int tp = nq * 2 + tpl;
                uint32_t bh[4], bl[4];
                uint32_t ba = brow + tp * 16 * (K2S * 2) + kt * 32;
                ldsm_x4(ba, bh);
                ldsm_x4(ba + 34816, bl);
                mma_f16(acc[2 * tpl],     ah, bh[0], bh[2]);
                mma_f16(acc[2 * tpl + 1], ah, bh[1], bh[3]);
                mma_f16(acc[2 * tpl],     ah, bl[0], bl[2]);
                mma_f16(acc[2 * tpl + 1], ah, bl[1], bl[3]);
            }
        }
        __syncthreads();   // all A/W reads done before A rewrite / W restage

        if (L < 2) {
            // start W(L+1) staging now — overlaps the epilogue below
            {
                const float4* src = (const float4*)g_wimg[L + 1];
                for (int i = tid; i < 69632 / 16; i += TPB)
                    cp_async16(sb + P2_W + i * 16, src + i);
                CP_COMMIT();
            }
            uint32_t* aH = (uint32_t*)(smem + P2_A);
#pragma unroll
            for (int nt2 = 0; nt2 < 4; ++nt2) {
                int colg = nq * 32 + nt2 * 8 + qc;
                int acol = nq * 16 + nt2 * 4 + (lane & 3);
#pragma unroll
                for (int h = 0; h < 2; ++h) {
                    float v0 = fast_tanh(acc[nt2][2 * h]     + sBias[L * 128 + colg]);
                    float v1 = fast_tanh(acc[nt2][2 * h + 1] + sBias[L * 128 + colg + 1]);
                    int row = rg * 16 + gr + 8 * h;
                    aH[row * (K2S / 2) + acol] = packh2(v0, v1);
                }
            }
        }
    }

    // final activations + output partials over this warp's 32 cols
    float p00 = 0.f, p01 = 0.f, p10 = 0.f, p11 = 0.f;
#pragma unroll
    for (int nt2 = 0; nt2 < 4; ++nt2) {
#pragma unroll
        for (int i = 0; i < 2; ++i) {
            int col = nq * 32 + nt2 * 8 + qc + i;
            float b = sBias[256 + col];
            float h0 = fast_tanh(acc[nt2][i] + b);
            float h1 = fast_tanh(acc[nt2][2 + i] + b);
            float w0 = sW4[col], w1 = sW4[128 + col];
            p00 = fmaf(h0, w0, p00); p01 = fmaf(h0, w1, p01);
            p10 = fmaf(h1, w0, p10); p11 = fmaf(h1, w1, p11);
        }
    }
#pragma unroll
    for (int m = 1; m <= 2; m <<= 1) {
        p00 += __shfl_xor_sync(0xffffffffu, p00, m);
        p01 += __shfl_xor_sync(0xffffffffu, p01, m);
        p10 += __shfl_xor_sync(0xffffffffu, p10, m);
        p11 += __shfl_xor_sync(0xffffffffu, p11, m);
    }
    if ((lane & 3) == 0) {
        int row0 = rg * 16 + gr;
        exch[(row0 * 4 + nq) * 2 + 0] = p00;
        exch[(row0 * 4 + nq) * 2 + 1] = p01;
        exch[((row0 + 8) * 4 + nq) * 2 + 0] = p10;
        exch[((row0 + 8) * 4 + nq) * 2 + 1] = p11;
    }
    __syncthreads();
    if (tid < 128) {
        int row = tid >> 1, o = tid & 1;
        long rowg = (long)blk * 64 + row;
        float v = exch[(row * 4 + 0) * 2 + o] + exch[(row * 4 + 1) * 2 + o]
                + exch[(row * 4 + 2) * 2 + o] + exch[(row * 4 + 3) * 2 + o] + sb4[o];
        out[rowg * 2 + o] = v;
    }
}

// ------------------------------------------------------------------- host ----
extern "C" void kernel_launch(void* const* d_in, const int* in_sizes, int n_in,
                              void* d_out, int out_size) {
    const float* X  = (const float*)d_in[0];
    const float* FB = (const float*)d_in[1];
    const float* W0 = (const float*)d_in[2];
    const float* b0 = (const float*)d_in[3];
    const float* W1 = (const float*)d_in[4];
    const float* b1 = (const float*)d_in[5];
    const float* W2 = (const float*)d_in[6];
    const float* b2 = (const float*)d_in[7];
    const float* W3 = (const float*)d_in[8];
    const float* b3 = (const float*)d_in[9];
    const float* W4 = (const float*)d_in[10];
    const float* b4 = (const float*)d_in[11];
    float* out = (float*)d_out;

    cudaFuncSetAttribute(pass1_kernel, cudaFuncAttributeMaxDynamicSharedMemorySize, P1_SMEM);
    cudaFuncSetAttribute(pass2_kernel, cudaFuncAttributeMaxDynamicSharedMemorySize, P2_SMEM);

    prep_img_kernel<<<64, 256>>>(W0, W1, W2, W3);
    pass1_kernel<<<NBLK2, TPB, P1_SMEM>>>(X, FB, b0);
    reduce_kernel<<<1, 1024>>>();
    pass2_kernel<<<NBLK2, TPB, P2_SMEM>>>(b1, b2, b3, W4, b4, out);
}